// round 4
// baseline (speedup 1.0000x reference)
#include <cuda_runtime.h>
#include <cuda_bf16.h>
#include <cstdint>

typedef unsigned long long ull;

#define BATCH 256
#define SEQ   128
#define EMBD  512
#define H2D   512
#define G2D   1536
#define HIDD  1024
#define G3D   3072
#define CTXDIM 64
#define VOC   32000
#define TLEN  40
#define SOSID 2

#define SWZ(o) ((o) ^ (((o)>>3)&0x70))

// ---------------- scratch (device globals) ----------------
__device__ float g_gx[2][SEQ*BATCH][G2D];
__device__ float g_h[2][2][BATCH*H2D];
__device__ float g_cgx[BATCH][G3D];
__device__ float g_hd[2][BATCH*HIDD];
__device__ float g_logits[BATCH][VOC];
__device__ int   g_prev[BATCH];
__device__ __align__(16) __nv_bfloat16 g_wbf[VOC*HIDD];          // b1 plane of wout (for logits)
__device__ __align__(16) __nv_bfloat16 g_emb3[3u*VOC*EMBD];      // emb split planes
__device__ __align__(16) __nv_bfloat16 g_wih3[2][3*G2D*EMBD];
__device__ __align__(16) __nv_bfloat16 g_whh3[2][3*G2D*H2D];
__device__ __align__(16) __nv_bfloat16 g_dwihx3[3*G3D*EMBD];
__device__ __align__(16) __nv_bfloat16 g_dwhh3[3*G3D*HIDD];
__device__ __align__(16) __nv_bfloat16 g_h3[2][2][3*BATCH*H2D];  // encoder h planes
__device__ __align__(16) __nv_bfloat16 g_hd3[2][3*BATCH*HIDD];   // decoder h planes

#define EPL   (VOC*EMBD)        // 16384000
#define WIHPL (G2D*EMBD)        // 786432
#define WHHPL (G2D*H2D)         // 786432
#define DWXPL (G3D*EMBD)        // 1572864
#define DWHPL (G3D*HIDD)        // 3145728
#define H3PL  (BATCH*H2D)       // 131072
#define HD3PL (BATCH*HIDD)      // 262144

// ---------------- helpers ----------------
__device__ __forceinline__ ull pk2(float lo, float hi){ ull r; asm("mov.b64 %0,{%1,%2};":"=l"(r):"f"(lo),"f"(hi)); return r; }
__device__ __forceinline__ void upk2(ull v, float& lo, float& hi){ asm("mov.b64 {%0,%1},%2;":"=f"(lo),"=f"(hi):"l"(v)); }
__device__ __forceinline__ ull ffma2(ull a, ull b, ull c){ ull d; asm("fma.rn.f32x2 %0,%1,%2,%3;":"=l"(d):"l"(a),"l"(b),"l"(c)); return d; }
__device__ __forceinline__ float sigf(float x){ return 1.0f/(1.0f + expf(-x)); }
__device__ __forceinline__ uint32_t s2u(const void* p){
  uint32_t a; asm("{ .reg .u64 t; cvta.to.shared.u64 t, %1; cvt.u32.u64 %0, t; }":"=r"(a):"l"(p)); return a;
}
__device__ __forceinline__ void ldmx4(uint32_t& r0,uint32_t& r1,uint32_t& r2,uint32_t& r3, uint32_t addr){
  asm volatile("ldmatrix.sync.aligned.m8n8.x4.shared.b16 {%0,%1,%2,%3}, [%4];"
    :"=r"(r0),"=r"(r1),"=r"(r2),"=r"(r3):"r"(addr));
}
__device__ __forceinline__ void mma16816(float* d, uint32_t a0,uint32_t a1,uint32_t a2,uint32_t a3, uint32_t b0,uint32_t b1){
  asm volatile("mma.sync.aligned.m16n8k16.row.col.f32.bf16.bf16.f32 "
    "{%0,%1,%2,%3}, {%4,%5,%6,%7}, {%8,%9}, {%0,%1,%2,%3};"
    :"+f"(d[0]),"+f"(d[1]),"+f"(d[2]),"+f"(d[3])
    :"r"(a0),"r"(a1),"r"(a2),"r"(a3),"r"(b0),"r"(b1));
}
__device__ __forceinline__ void split3(float x, __nv_bfloat16& b1, __nv_bfloat16& b2, __nv_bfloat16& b3){
  b1 = __float2bfloat16(x);
  float r1 = x - __bfloat162float(b1);
  b2 = __float2bfloat16(r1);
  float r2 = r1 - __bfloat162float(b2);
  b3 = __float2bfloat16(r2);
}

// significant plane products for 3-way split
__device__ const int PAarr[6] = {0,0,1,1,0,2};
__device__ const int PBarr[6] = {0,1,0,1,2,0};

// ---------------- init ----------------
__global__ __launch_bounds__(256) void k_init(){
  int i = blockIdx.x*256 + threadIdx.x;   // grid 1024 -> 262144 threads
  g_hd[0][i] = 0.f;
  __nv_bfloat16 z = __float2bfloat16(0.f);
  g_hd3[0][i] = z; g_hd3[0][i + HD3PL] = z; g_hd3[0][i + 2*HD3PL] = z;
  if (i < H3PL){
    g_h[0][0][i] = 0.f; g_h[1][0][i] = 0.f;
    #pragma unroll
    for (int p=0;p<3;p++){ g_h3[0][0][p*H3PL+i] = z; g_h3[1][0][p*H3PL+i] = z; }
  }
  if (i < BATCH) g_prev[i] = SOSID;
}

// ---------------- split precompute ----------------
__global__ __launch_bounds__(256) void k_split3c(const float* __restrict__ src, int sel, int n){
  int base = (blockIdx.x*256 + threadIdx.x)*4;
  if (base >= n) return;
  __nv_bfloat16* dst = (sel==0)? g_emb3 : (sel==1)? g_wih3[0] : (sel==2)? g_wih3[1] :
                       (sel==3)? g_whh3[0] : (sel==4)? g_whh3[1] : g_dwhh3;
  float4 v = *(const float4*)(src + base);
  float x[4] = {v.x, v.y, v.z, v.w};
  __nv_bfloat16 p1[4], p2[4], p3[4];
  #pragma unroll
  for (int j=0;j<4;j++) split3(x[j], p1[j], p2[j], p3[j]);
  *(__nv_bfloat162*)(dst + base)       = __halves2bfloat162(p1[0],p1[1]);
  *(__nv_bfloat162*)(dst + base+2)     = __halves2bfloat162(p1[2],p1[3]);
  *(__nv_bfloat162*)(dst + n + base)   = __halves2bfloat162(p2[0],p2[1]);
  *(__nv_bfloat162*)(dst + n + base+2) = __halves2bfloat162(p2[2],p2[3]);
  *(__nv_bfloat162*)(dst + 2*n + base)   = __halves2bfloat162(p3[0],p3[1]);
  *(__nv_bfloat162*)(dst + 2*n + base+2) = __halves2bfloat162(p3[2],p3[3]);
}
// strided: dec_wih cols [0,512) of stride 1600 -> g_dwihx3
__global__ __launch_bounds__(256) void k_split3s(const float* __restrict__ src){
  int base = (blockIdx.x*256 + threadIdx.x)*4;      // over 3072*512
  if (base >= G3D*EMBD) return;
  int r = base >> 9, cc = base & 511;
  float4 v = *(const float4*)(src + (size_t)r*1600 + cc);
  float x[4] = {v.x, v.y, v.z, v.w};
  __nv_bfloat16 p1[4], p2[4], p3[4];
  #pragma unroll
  for (int j=0;j<4;j++) split3(x[j], p1[j], p2[j], p3[j]);
  __nv_bfloat16* dst = g_dwihx3;
  *(__nv_bfloat162*)(dst + base)       = __halves2bfloat162(p1[0],p1[1]);
  *(__nv_bfloat162*)(dst + base+2)     = __halves2bfloat162(p1[2],p1[3]);
  *(__nv_bfloat162*)(dst + DWXPL + base)   = __halves2bfloat162(p2[0],p2[1]);
  *(__nv_bfloat162*)(dst + DWXPL + base+2) = __halves2bfloat162(p2[2],p2[3]);
  *(__nv_bfloat162*)(dst + 2*DWXPL + base)   = __halves2bfloat162(p3[0],p3[1]);
  *(__nv_bfloat162*)(dst + 2*DWXPL + base+2) = __halves2bfloat162(p3[2],p3[3]);
}
// wout -> b1 plane (logits only need bf16; argmax rescored exactly)
__global__ __launch_bounds__(256) void k_wconv(const float* __restrict__ w){
  size_t i = (size_t)blockIdx.x*256 + threadIdx.x;
  float4 v = ((const float4*)w)[i];
  __nv_bfloat162* dst = (__nv_bfloat162*)g_wbf;
  dst[2*i]   = __floats2bfloat162_rn(v.x, v.y);
  dst[2*i+1] = __floats2bfloat162_rn(v.z, v.w);
}

// ================= encoder input GEMM: split-3 HMMA =================
// C[s*B+b][n] = emb[id]*wih^T + bih.  Tile 128x128, K=512 (8 chunks of 64).
__global__ __launch_bounds__(256,1) void k_encx3(const int* __restrict__ ids,
      const float* __restrict__ bf_, const float* __restrict__ bb_){
  extern __shared__ char smraw[];
  char* sm = (char*)(((uintptr_t)smraw + 1023) & ~(uintptr_t)1023);
  const int dir = blockIdx.z;
  const float* bias = dir ? bb_ : bf_;
  const __nv_bfloat16* WB = g_wih3[dir];
  __shared__ int pid[128];
  const int t = threadIdx.x, lane = t&31, wid = t>>5;
  const int m0 = blockIdx.y*128, n0 = blockIdx.x*128;
  if (t < 128){
    int r = m0 + t; int ss = r>>8, b = r&255;
    int st = dir ? (SEQ-1-ss) : ss;
    pid[t] = ids[b*SEQ + st];
  }
  __syncthreads();
  const uint32_t SB = s2u(sm);
  const int mbase = (wid&1)*64, nbase = (wid>>1)*32;
  float acc[4][4][4];
  #pragma unroll
  for(int a=0;a<4;a++)
    #pragma unroll
    for(int b=0;b<4;b++)
      #pragma unroll
      for(int e=0;e<4;e++) acc[a][b][e]=0.f;
  uint32_t aoff[3][4], boff[3][2];
  #pragma unroll
  for (int p=0;p<3;p++){
    #pragma unroll
    for (int mt=0;mt<4;mt++){
      uint32_t row = mbase + mt*16 + (lane&15);
      uint32_t off = p*16384u + row*128u + (lane>>4)*16u;
      aoff[p][mt] = SWZ(off);
    }
    #pragma unroll
    for (int nt2=0;nt2<2;nt2++){
      uint32_t rowu = nbase + nt2*16 + (lane&7) + ((lane>>4)&1)*8;
      uint32_t off = 49152u + p*16384u + rowu*128u + ((lane>>3)&1)*16u;
      boff[p][nt2] = SWZ(off);
    }
  }
  for (int c=0;c<8;c++){
    #pragma unroll
    for (int i=0;i<12;i++){
      int idx = t + i*256;
      int p = idx>>10, rem = idx&1023, row = rem>>3, seg = rem&7;
      uint32_t off = p*16384u + row*128u + seg*16u;
      *(uint4*)(sm + SWZ(off)) = *(const uint4*)((const char*)g_emb3 +
          ((size_t)p*EPL + (size_t)pid[row]*EMBD)*2 + c*128 + seg*16);
    }
    #pragma unroll
    for (int i=0;i<12;i++){
      int idx = t + i*256;
      int p = idx>>10, rem = idx&1023, row = rem>>3, seg = rem&7;
      uint32_t off = 49152u + p*16384u + row*128u + seg*16u;
      *(uint4*)(sm + SWZ(off)) = *(const uint4*)((const char*)WB +
          ((size_t)p*WIHPL + (size_t)(n0+row)*EMBD)*2 + c*128 + seg*16);
    }
    __syncthreads();
    #pragma unroll
    for (int ks=0;ks<4;ks++){
      const uint32_t kx = (uint32_t)(ks<<5);
      uint32_t bfr[3][2][4];
      #pragma unroll
      for (int p=0;p<3;p++)
        #pragma unroll
        for (int nt2=0;nt2<2;nt2++)
          ldmx4(bfr[p][nt2][0],bfr[p][nt2][1],bfr[p][nt2][2],bfr[p][nt2][3], SB + (boff[p][nt2]^kx));
      #pragma unroll
      for (int mt=0;mt<4;mt++){
        uint32_t a[3][4];
        #pragma unroll
        for (int p=0;p<3;p++)
          ldmx4(a[p][0],a[p][1],a[p][2],a[p][3], SB + (aoff[p][mt]^kx));
        #pragma unroll
        for (int pr=0;pr<6;pr++){
          const int pa = PAarr[pr], pb = PBarr[pr];
          #pragma unroll
          for (int nt=0;nt<4;nt++)
            mma16816(acc[mt][nt], a[pa][0],a[pa][1],a[pa][2],a[pa][3],
                     bfr[pb][nt>>1][(nt&1)*2], bfr[pb][nt>>1][(nt&1)*2+1]);
        }
      }
    }
    __syncthreads();
  }
  #pragma unroll
  for (int mt=0;mt<4;mt++){
    int r0 = m0 + mbase + mt*16 + (lane>>2);
    #pragma unroll
    for (int nt=0;nt<4;nt++){
      int c0 = n0 + nbase + nt*8 + (lane&3)*2;
      float b0v = bias[c0], b1v = bias[c0+1];
      g_gx[dir][r0][c0]     = acc[mt][nt][0] + b0v;
      g_gx[dir][r0][c0+1]   = acc[mt][nt][1] + b1v;
      g_gx[dir][r0+8][c0]   = acc[mt][nt][2] + b0v;
      g_gx[dir][r0+8][c0+1] = acc[mt][nt][3] + b1v;
    }
  }
}

// ---- shared inner loop for gate-grouped kernels: warp m16 x u16, 3 gates ----
__device__ __forceinline__ void inner_3g(float acc[3][2][4], uint32_t SB,
      const uint32_t aoff[3], const uint32_t boff[3][3]){
  #pragma unroll
  for (int ks=0;ks<4;ks++){
    const uint32_t kx = (uint32_t)(ks<<5);
    uint32_t a[3][4];
    #pragma unroll
    for (int p=0;p<3;p++)
      ldmx4(a[p][0],a[p][1],a[p][2],a[p][3], SB + (aoff[p]^kx));
    uint32_t bfr[3][3][4];
    #pragma unroll
    for (int g=0;g<3;g++)
      #pragma unroll
      for (int p=0;p<3;p++)
        ldmx4(bfr[g][p][0],bfr[g][p][1],bfr[g][p][2],bfr[g][p][3], SB + (boff[g][p]^kx));
    #pragma unroll
    for (int pr=0;pr<6;pr++){
      const int pa = PAarr[pr], pb = PBarr[pr];
      #pragma unroll
      for (int g=0;g<3;g++){
        mma16816(acc[g][0], a[pa][0],a[pa][1],a[pa][2],a[pa][3], bfr[g][pb][0],bfr[g][pb][1]);
        mma16816(acc[g][1], a[pa][0],a[pa][1],a[pa][2],a[pa][3], bfr[g][pb][2],bfr[g][pb][3]);
      }
    }
  }
}

// ================= encoder recurrence step: fused split-3 HMMA + GRU =================
// grid (16 u-tiles, 4 m-tiles, 2 dirs). CTA: M=64 batch x 32 units (3 gates).
__global__ __launch_bounds__(256,1) void k_step_enc(int s,
      const float* __restrict__ bhf, const float* __restrict__ bhb){
  extern __shared__ char smraw[];
  char* sm = (char*)(((uintptr_t)smraw + 1023) & ~(uintptr_t)1023);
  const int dir = blockIdx.z;
  const float* bhh = dir ? bhb : bhf;
  const int pin = s&1, pout = pin^1;
  const __nv_bfloat16* hA = g_h3[dir][pin];
  const __nv_bfloat16* WB = g_whh3[dir];
  const int t = threadIdx.x, lane = t&31, wid = t>>5;
  const int u0 = blockIdx.x*32, m0 = blockIdx.y*64;
  const int mw = wid&3, uw = wid>>2;
  const uint32_t SB = s2u(sm);
  float acc[3][2][4];
  #pragma unroll
  for(int g=0;g<3;g++)
    #pragma unroll
    for(int f=0;f<2;f++)
      #pragma unroll
      for(int e=0;e<4;e++) acc[g][f][e]=0.f;
  uint32_t aoff[3], boff[3][3];
  #pragma unroll
  for (int p=0;p<3;p++){
    uint32_t row = mw*16 + (lane&15);
    uint32_t off = p*8192u + row*128u + (lane>>4)*16u;
    aoff[p] = SWZ(off);
  }
  #pragma unroll
  for (int g=0;g<3;g++)
    #pragma unroll
    for (int p=0;p<3;p++){
      uint32_t rowu = uw*16 + (lane&7) + ((lane>>4)&1)*8;
      uint32_t off = 24576u + p*12288u + g*4096u + rowu*128u + ((lane>>3)&1)*16u;
      boff[g][p] = SWZ(off);
    }
  for (int c=0;c<8;c++){
    #pragma unroll
    for (int i=0;i<6;i++){
      int idx = t + i*256;
      int p = idx>>9, rem = idx&511, row = rem>>3, seg = rem&7;
      uint32_t off = p*8192u + row*128u + seg*16u;
      *(uint4*)(sm + SWZ(off)) = *(const uint4*)((const char*)hA +
          ((size_t)p*H3PL + (size_t)(m0+row)*H2D)*2 + c*128 + seg*16);
    }
    #pragma unroll
    for (int i=0;i<9;i++){
      int idx = t + i*256;
      int p = idx/768, rem = idx - p*768;
      int g = rem>>8, r2 = rem&255, row = r2>>3, seg = r2&7;
      uint32_t off = 24576u + p*12288u + g*4096u + row*128u + seg*16u;
      *(uint4*)(sm + SWZ(off)) = *(const uint4*)((const char*)WB +
          ((size_t)p*WHHPL + (size_t)(g*H2D + u0 + row)*H2D)*2 + c*128 + seg*16);
    }
    __syncthreads();
    inner_3g(acc, SB, aoff, boff);
    __syncthreads();
  }
  // GRU epilogue
  const int rbase = m0 + mw*16 + (lane>>2);
  const int ubase = u0 + uw*16 + (lane&3)*2;
  #pragma unroll
  for (int nt=0; nt<2; nt++)
    #pragma unroll
    for (int rr=0; rr<2; rr++)
      #pragma unroll
      for (int ee=0; ee<2; ee++){
        int row = rbase + rr*8;
        int u = ubase + nt*8 + ee;
        int ci = rr*2 + ee;
        float ghr = acc[0][nt][ci] + bhh[u];
        float ghz = acc[1][nt][ci] + bhh[H2D+u];
        float ghn = acc[2][nt][ci] + bhh[2*H2D+u];
        const float* gx = g_gx[dir][s*BATCH + row];
        float r_ = sigf(gx[u] + ghr);
        float z_ = sigf(gx[H2D+u] + ghz);
        float n_ = tanhf(gx[2*H2D+u] + r_*ghn);
        float ho = g_h[dir][pin][row*H2D + u];
        float hv = (1.f - z_)*n_ + z_*ho;
        g_h[dir][pout][row*H2D + u] = hv;
        __nv_bfloat16 b1,b2,b3; split3(hv,b1,b2,b3);
        g_h3[dir][pout][0*H3PL + row*H2D + u] = b1;
        g_h3[dir][pout][1*H3PL + row*H2D + u] = b2;
        g_h3[dir][pout][2*H3PL + row*H2D + u] = b3;
      }
}

// ================= decoder step: split-3 HMMA (2 phases) + GRU =================
// grid (32 u-tiles, 4 m-tiles). CTA: M=64 x 32 units.
__global__ __launch_bounds__(256,1) void k_dec3(int step, const float* __restrict__ dbhh){
  extern __shared__ char smraw[];
  char* sm = (char*)(((uintptr_t)smraw + 1023) & ~(uintptr_t)1023);
  __shared__ int pid[64];
  const int pin = step&1, pout = pin^1;
  const int t = threadIdx.x, lane = t&31, wid = t>>5;
  const int u0 = blockIdx.x*32, m0 = blockIdx.y*64;
  if (t < 64) pid[t] = g_prev[m0 + t];
  const int mw = wid&3, uw = wid>>2;
  const uint32_t SB = s2u(sm);
  float accx[3][2][4], acch[3][2][4];
  #pragma unroll
  for(int g=0;g<3;g++)
    #pragma unroll
    for(int f=0;f<2;f++)
      #pragma unroll
      for(int e=0;e<4;e++){ accx[g][f][e]=0.f; acch[g][f][e]=0.f; }
  uint32_t aoff[3], boff[3][3];
  #pragma unroll
  for (int p=0;p<3;p++){
    uint32_t row = mw*16 + (lane&15);
    uint32_t off = p*8192u + row*128u + (lane>>4)*16u;
    aoff[p] = SWZ(off);
  }
  #pragma unroll
  for (int g=0;g<3;g++)
    #pragma unroll
    for (int p=0;p<3;p++){
      uint32_t rowu = uw*16 + (lane&7) + ((lane>>4)&1)*8;
      uint32_t off = 24576u + p*12288u + g*4096u + rowu*128u + ((lane>>3)&1)*16u;
      boff[g][p] = SWZ(off);
    }
  __syncthreads();   // pid ready
  // phase 1: x = emb[prev], K=512, W = dwih[:, :512]
  for (int c=0;c<8;c++){
    #pragma unroll
    for (int i=0;i<6;i++){
      int idx = t + i*256;
      int p = idx>>9, rem = idx&511, row = rem>>3, seg = rem&7;
      uint32_t off = p*8192u + row*128u + seg*16u;
      *(uint4*)(sm + SWZ(off)) = *(const uint4*)((const char*)g_emb3 +
          ((size_t)p*EPL + (size_t)pid[row]*EMBD)*2 + c*128 + seg*16);
    }
    #pragma unroll
    for (int i=0;i<9;i++){
      int idx = t + i*256;
      int p = idx/768, rem = idx - p*768;
      int g = rem>>8, r2 = rem&255, row = r2>>3, seg = r2&7;
      uint32_t off = 24576u + p*12288u + g*4096u + row*128u + seg*16u;
      *(uint4*)(sm + SWZ(off)) = *(const uint4*)((const char*)g_dwihx3 +
          ((size_t)p*DWXPL + (size_t)(g*HIDD + u0 + row)*EMBD)*2 + c*128 + seg*16);
    }
    __syncthreads();
    inner_3g(accx, SB, aoff, boff);
    __syncthreads();
  }
  // phase 2: h, K=1024, W = dwhh
  const __nv_bfloat16* hA = g_hd3[pin];
  for (int c=0;c<16;c++){
    #pragma unroll
    for (int i=0;i<6;i++){
      int idx = t + i*256;
      int p = idx>>9, rem = idx&511, row = rem>>3, seg = rem&7;
      uint32_t off = p*8192u + row*128u + seg*16u;
      *(uint4*)(sm + SWZ(off)) = *(const uint4*)((const char*)hA +
          ((size_t)p*HD3PL + (size_t)(m0+row)*HIDD)*2 + c*128 + seg*16);
    }
    #pragma unroll
    for (int i=0;i<9;i++){
      int idx = t + i*256;
      int p = idx/768, rem = idx - p*768;
      int g = rem>>8, r2 = rem&255, row = r2>>3, seg = r2&7;
      uint32_t off = 24576u + p*12288u + g*4096u + row*128u + seg*16u;
      *(uint4*)(sm + SWZ(off)) = *(const uint4*)((const char*)g_dwhh3 +
          ((size_t)p*DWHPL + (size_t)(g*HIDD + u0 + row)*HIDD)*2 + c*128 + seg*16);
    }
    __syncthreads();
    inner_3g(acch, SB, aoff, boff);
    __syncthreads();
  }
  // GRU epilogue
  const int rbase = m0 + mw*16 + (lane>>2);
  const int ubase = u0 + uw*16 + (lane&3)*2;
  #pragma unroll
  for (int nt=0; nt<2; nt++)
    #pragma unroll
    for (int rr=0; rr<2; rr++)
      #pragma unroll
      for (int ee=0; ee<2; ee++){
        int row = rbase + rr*8;
        int u = ubase + nt*8 + ee;
        int ci = rr*2 + ee;
        const float* cg = g_cgx[row];
        float gxr = accx[0][nt][ci] + cg[u];
        float gxz = accx[1][nt][ci] + cg[HIDD+u];
        float gxn = accx[2][nt][ci] + cg[2*HIDD+u];
        float ghr = acch[0][nt][ci] + dbhh[u];
        float ghz = acch[1][nt][ci] + dbhh[HIDD+u];
        float ghn = acch[2][nt][ci] + dbhh[2*HIDD+u];
        float r_ = sigf(gxr + ghr);
        float z_ = sigf(gxz + ghz);
        float n_ = tanhf(gxn + r_*ghn);
        float ho = g_hd[pin][row*HIDD + u];
        float hv = (1.f - z_)*n_ + z_*ho;
        g_hd[pout][row*HIDD + u] = hv;
        __nv_bfloat16 b1,b2,b3; split3(hv,b1,b2,b3);
        g_hd3[pout][0*HD3PL + row*HIDD + u] = b1;
        g_hd3[pout][1*HD3PL + row*HIDD + u] = b2;
        g_hd3[pout][2*HD3PL + row*HIDD + u] = b3;
      }
}

// ================= decoder constant gx: cgx = [enc_ctx | ctxv] @ Wih[:,512:].T + bih =================
__global__ __launch_bounds__(256) void k_cgx(const float* __restrict__ ctxv,
      const float* __restrict__ dwih, const float* __restrict__ dbih){
  __shared__ float As[16][68];
  __shared__ float Bs[16][68];
  const int t = threadIdx.x;
  const int m0 = blockIdx.y*64, n0 = blockIdx.x*64;
  const int lr = t>>2, lk4 = (t&3)*4;
  const int tx = t&15, ty = t>>4;
  const int b  = m0 + lr;
  const float* brow = dwih + (size_t)(n0+lr)*1600 + 512;
  ull acc[4][2];
  #pragma unroll
  for(int i=0;i<4;i++){acc[i][0]=0ull;acc[i][1]=0ull;}
  for(int k0=0;k0<1088;k0+=16){
    int j = k0 + lk4;
    float4 av;
    if (j < 1024){
      const float* hsrc = (b < 128) ? g_h[0][0] : g_h[1][0];
      int b2 = (b < 128) ? b : b - 128;
      av = *(const float4*)(hsrc + (2*b2 + (j>=512 ? 1 : 0))*H2D + (j & 511));
    } else {
      av = *(const float4*)(ctxv + b*CTXDIM + (j - 1024));
    }
    As[lk4+0][lr]=av.x; As[lk4+1][lr]=av.y; As[lk4+2][lr]=av.z; As[lk4+3][lr]=av.w;
    float4 bv = *(const float4*)(brow + k0 + lk4);
    Bs[lk4+0][lr]=bv.x; Bs[lk4+1][lr]=bv.y; Bs[lk4+2][lr]=bv.z; Bs[lk4+3][lr]=bv.w;
    __syncthreads();
    #pragma unroll
    for(int k=0;k<16;k++){
      float4 a = *(const float4*)&As[k][ty*4];
      float4 b4 = *(const float4*)&Bs[k][tx*4];
      ull b01 = pk2(b4.x,b4.y), b23 = pk2(b4.z,b4.w);
      ull a0=pk2(a.x,a.x), a1=pk2(a.y,a.y), a2=pk2(a.z,a.z), a3=pk2(a.w,a.w);
      acc[0][0]=ffma2(a0,b01,acc[0][0]); acc[0][1]=ffma2(a0,b23,acc[0][1]);
      acc[1][0]=ffma2(a1,b01,acc[1][0]); acc[1][1]=ffma2(a1,b23,acc[1][1]);
      acc[2][0]=ffma2(a2,b01,acc[2][0]); acc[2][1]=ffma2(a2,b23,acc[2][1]);
      acc[3][0]=ffma2(a3,b01,acc[3][0]); acc[3][1]=ffma2(a3,b23,acc[3][1]);
    }
    __syncthreads();
  }
  const int c0 = n0 + tx*4;
  float4 b4 = *(const float4*)(dbih + c0);
  #pragma unroll
  for(int i=0;i<4;i++){
    int row = m0 + ty*4 + i;
    float4 o; upk2(acc[i][0], o.x, o.y); upk2(acc[i][1], o.z, o.w);
    o.x+=b4.x; o.y+=b4.y; o.z+=b4.z; o.w+=b4.w;
    *(float4*)&g_cgx[row][c0] = o;
  }
}

// ================= logits via bf16 HMMA =================
__global__ __launch_bounds__(256) void k_loghmma(int pp, const float* __restrict__ bout){
  __shared__ __align__(1024) char Asm[16384];
  __shared__ __align__(1024) char Bsm[16384];
  const __nv_bfloat16* hbf = g_hd3[pp];   // plane 0 = bf16(h)
  const int t = threadIdx.x;
  const int lane = t&31, wid = t>>5;
  const int mblk = blockIdx.y*128, nblk = blockIdx.x*128;
  const int mbase = (wid&1)*64, nbase = (wid>>1)*32;
  const uint32_t Au = s2u(Asm), Bu = s2u(Bsm);
  float acc[4][4][4];
  #pragma unroll
  for(int mt=0;mt<4;mt++)
    #pragma unroll
    for(int nt=0;nt<4;nt++)
      #pragma unroll
      for(int e=0;e<4;e++) acc[mt][nt][e]=0.f;
  uint32_t aoff[4], boff[2];
  #pragma unroll
  for(int mt=0;mt<4;mt++){
    uint32_t row = mbase + mt*16 + (lane&15);
    uint32_t off = row*128 + (lane>>4)*16;
    aoff[mt] = SWZ(off);
  }
  #pragma unroll
  for(int nt2=0;nt2<2;nt2++){
    uint32_t row = nbase + nt2*16 + (lane&7) + ((lane>>4)&1)*8;
    uint32_t off = row*128 + ((lane>>3)&1)*16;
    boff[nt2] = SWZ(off);
  }
  for(int c=0;c<16;c++){
    #pragma unroll
    for(int i=0;i<4;i++){
      int idx = t + i*256;
      int row = idx>>3, unit = idx&7;
      uint32_t off = row*128 + unit*16;
      uint32_t sw = SWZ(off);
      *(uint4*)(Asm + sw) = *(const uint4*)((const char*)hbf + (size_t)(mblk+row)*2048 + c*128 + unit*16);
      *(uint4*)(Bsm + sw) = *(const uint4*)((const char*)g_wbf + (size_t)(nblk+row)*2048 + c*128 + unit*16);
    }
    __syncthreads();
    #pragma unroll
    for(int ks=0;ks<4;ks++){
      const uint32_t kx = (uint32_t)(ks<<5);
      uint32_t a[4][4], b[2][4];
      #pragma unroll
      for(int mt=0;mt<4;mt++)
        ldmx4(a[mt][0],a[mt][1],a[mt][2],a[mt][3], Au + (aoff[mt]^kx));
      #pragma unroll
      for(int nt2=0;nt2<2;nt2++)
        ldmx4(b[nt2][0],b[nt2][1],b[nt2][2],b[nt2][3], Bu + (boff[nt2]^kx));
      #pragma unroll
      for(int mt=0;mt<4;mt++)
        #pragma unroll
        for(int nt=0;nt<4;nt++)
          mma16816(acc[mt][nt], a[mt][0],a[mt][1],a[mt][2],a[mt][3],
                   b[nt>>1][(nt&1)*2], b[nt>>1][(nt&1)*2+1]);
    }
    __syncthreads();
  }
  #pragma unroll
  for(int mt=0;mt<4;mt++){
    int r0 = mblk + mbase + mt*16 + (lane>>2);
    #pragma unroll
    for(int nt=0;nt<4;nt++){
      int c0 = nblk + nbase + nt*8 + (lane&3)*2;
      float b0v = bout[c0], b1v = bout[c0+1];
      g_logits[r0][c0]     = acc[mt][nt][0] + b0v;
      g_logits[r0][c0+1]   = acc[mt][nt][1] + b1v;
      g_logits[r0+8][c0]   = acc[mt][nt][2] + b0v;
      g_logits[r0+8][c0+1] = acc[mt][nt][3] + b1v;
    }
  }
}

// ================= argmax + exact fp32 rescore + log-softmax =================
__global__ __launch_bounds__(256) void k_argmax(int step, int pp,
      const float* __restrict__ wout, const float* __restrict__ bout, float* __restrict__ out){
  const int b = blockIdx.x, tid = threadIdx.x;
  const int wid = tid>>5, lane = tid&31;
  const float* lg = g_logits[b];
  __shared__ float sv[256]; __shared__ int si[256];
  __shared__ float s1[256], s2a[256];
  float mv=-1e30f; int mi=0; float a1=0.f, a2=0.f;
  for (int i=tid;i<VOC;i+=256){ float v=lg[i]; a1+=v; a2+=v*v; if(v>mv){mv=v;mi=i;} }
  sv[tid]=mv; si[tid]=mi; s1[tid]=a1; s2a[tid]=a2; __syncthreads();
  for(int o=128;o>0;o>>=1){
    if(tid<o){
      if(sv[tid+o]>sv[tid]||(sv[tid+o]==sv[tid]&&si[tid+o]<si[tid])){sv[tid]=sv[tid+o];si[tid]=si[tid+o];}
      s1[tid]+=s1[tid+o]; s2a[tid]+=s2a[tid+o];
    }
    __syncthreads();
  }
  const float gmax=sv[0]; const int gidx=si[0];
  const float mean=s1[0]/VOC;
  const float var=fmaxf(s2a[0]/VOC-mean*mean,0.f);
  const float margin=0.05f*sqrtf(var)+1e-6f;
  __shared__ int cnt; __shared__ int cands[128]; __shared__ float cval[128];
  if(tid==0){cnt=1;cands[0]=gidx;}
  __syncthreads();
  float ls=0.f;
  for(int i=tid;i<VOC;i+=256){
    float v = lg[i];
    ls += expf(v-gmax);
    if(v>=gmax-margin && i!=gidx){ int p=atomicAdd(&cnt,1); if(p<128) cands[p]=i; }
  }
  sv[tid]=ls; __syncthreads();
  for(int o=128;o>0;o>>=1){ if(tid<o) sv[tid]+=sv[tid+o]; __syncthreads(); }
  const float ssum=sv[0];
  const int nc = min(cnt,128);
  const float* hrow = g_hd[pp] + (size_t)b*HIDD;
  for(int j=wid;j<nc;j+=8){
    const float* wr = wout + (size_t)cands[j]*HIDD;
    float s=0.f;
    for(int k=lane;k<HIDD;k+=32) s += hrow[k]*wr[k];
    #pragma unroll
    for(int o=16;o>0;o>>=1) s += __shfl_xor_sync(0xffffffffu,s,o);
    if(lane==0) cval[j]=s+bout[cands[j]];
  }
  __syncthreads();
  if(tid==0){
    float best=-1e30f; int bi=VOC;
    for(int j=0;j<nc;j++){
      float v=cval[j]; int id=cands[j];
      if(v>best||(v==best&&id<bi)){best=v;bi=id;}
    }
    float sel = expf(best-gmax)/ssum;
    float lp = logf(sel+1e-12f);
    out[b*TLEN+step]=(float)bi;
    out[BATCH*TLEN+b*TLEN+step]=lp;
    g_prev[b]=bi;
  }
}

// ================= launch =================
extern "C" void kernel_launch(void* const* d_in, const int* in_sizes, int n_in,
                              void* d_out, int out_size) {
  const int*   ids   = (const int*)  d_in[0];
  const float* ctxv  = (const float*)d_in[1];
  const float* emb   = (const float*)d_in[2];
  const float* ewihf = (const float*)d_in[3];
  const float* ewhhf = (const float*)d_in[4];
  const float* ebihf = (const float*)d_in[5];
  const float* ebhhf = (const float*)d_in[6];
  const float* ewihb = (const float*)d_in[7];
  const float* ewhhb = (const float*)d_in[8];
  const float* ebihb = (const float*)d_in[9];
  const float* ebhhb = (const float*)d_in[10];
  const float* dwih  = (const float*)d_in[11];
  const float* dwhh  = (const float*)d_in[12];
  const float* dbih  = (const float*)d_in[13];
  const float* dbhh  = (const float*)d_in[14];
  const float* wout  = (const float*)d_in[15];
  const float* bout  = (const float*)d_in[16];
  float* out = (float*)d_out;

  cudaFuncSetAttribute(k_encx3,   cudaFuncAttributeMaxDynamicSharedMemorySize, 99328);
  cudaFuncSetAttribute(k_step_enc,cudaFuncAttributeMaxDynamicSharedMemorySize, 62464);
  cudaFuncSetAttribute(k_dec3,    cudaFuncAttributeMaxDynamicSharedMemorySize, 62464);

  k_init<<<1024, 256>>>();
  k_split3c<<<16000, 256>>>(emb,   0, VOC*EMBD);
  k_split3c<<<768,   256>>>(ewihf, 1, G2D*EMBD);
  k_split3c<<<768,   256>>>(ewihb, 2, G2D*EMBD);
  k_split3c<<<768,   256>>>(ewhhf, 3, G2D*H2D);
  k_split3c<<<768,   256>>>(ewhhb, 4, G2D*H2D);
  k_split3c<<<3072,  256>>>(dwhh,  5, G3D*HIDD);
  k_split3s<<<1536,  256>>>(dwih);
  k_wconv<<<VOC*HIDD/1024, 256>>>(wout);

  k_encx3<<<dim3(G2D/128, (SEQ*BATCH)/128, 2), 256, 99328>>>(ids, ebihf, ebihb);
  for (int s = 0; s < SEQ; s++)
    k_step_enc<<<dim3(H2D/32, BATCH/64, 2), 256, 62464>>>(s, ebhhf, ebhhb);
  k_cgx<<<dim3(G3D/64, BATCH/64), 256>>>(ctxv, dwih, dbih);
  for (int t = 0; t < TLEN; t++){
    k_dec3<<<dim3(HIDD/32, BATCH/64), 256, 62464>>>(t, dbhh);
    k_loghmma<<<dim3(VOC/128, BATCH/128), 256>>>((t+1)&1, bout);
    k_argmax<<<BATCH, 256>>>(t, (t+1)&1, wout, bout, out);
  }
}